// round 5
// baseline (speedup 1.0000x reference)
#include <cuda_runtime.h>
#include <cuda_bf16.h>
#include <stdint.h>
#include <math.h>

// ---------------- problem constants ----------------
#define BB   4
#define TT   2048
#define DD   2048
#define HH   8
#define DH   256
#define TW   4
#define BT   (BB*TT)          // 8192
#define NC   32               // scan chunks
#define CL   (TT/NC)          // 64
#define NELEM (BT*DD)         // 16,777,216
#define CT   16               // conv timesteps per thread

// ---------------- GEMM tiling ----------------
#define TM   128
#define TN   256
#define TKC  64                        // bf16 K elems per chunk (128B row)
#define AH_OFF 0
#define AL_OFF (TM*128)                // 16384
#define BH_OFF (2*TM*128)              // 32768
#define BL_OFF (2*TM*128 + TN*128)     // 65536
#define STAGE_BYTES (2*TM*128 + 2*TN*128)   // 98304
#define SMEM_GEMM (2*STAGE_BYTES)           // 196608

// ---------------- device scratch ----------------
__device__ float g_y [NELEM];
__device__ float g_xp[NELEM];
__device__ float g_nx[NELEM];
__device__ float g_na[NELEM];
__device__ float g_Ac[BB*NC*DD];
__device__ float g_Bc[BB*NC*DD];
__device__ float g_h0[BB*NC*DD];
// bf16 hi/lo buffers (uint4-backed for 16B alignment)
__device__ uint4 g_xh_raw [NELEM/8];
__device__ uint4 g_xl_raw [NELEM/8];
__device__ uint4 g_xch_raw[NELEM/8];
__device__ uint4 g_xcl_raw[NELEM/8];
__device__ uint4 g_zh_raw [NELEM/8];
__device__ uint4 g_zl_raw [NELEM/8];
__device__ uint4 g_wh_raw [3*DD*DD/8];
__device__ uint4 g_wl_raw [3*DD*DD/8];
__device__ uint4 g_gwh_raw[HH*512*DH/8];   // interleaved gate weights hi
__device__ uint4 g_gwl_raw[HH*512*DH/8];   // lo

// ---------------- helpers ----------------
__device__ __forceinline__ float gelu_tanh(float x) {
    float x3 = x * x * x;
    return 0.5f * x * (1.0f + tanhf(0.7978845608028654f * (x + 0.044715f * x3)));
}
__device__ __forceinline__ float sigmoidf(float x) { return 1.0f / (1.0f + expf(-x)); }

__device__ __forceinline__ uint32_t smem_u32(const void* p) {
    uint32_t a;
    asm("{ .reg .u64 t; cvta.to.shared.u64 t, %1; cvt.u32.u64 %0, t; }" : "=r"(a) : "l"(p));
    return a;
}
__device__ __forceinline__ void cp16(uint32_t dst, const void* src) {
    asm volatile("cp.async.cg.shared.global [%0], [%1], 16;" :: "r"(dst), "l"(src));
}
__device__ __forceinline__ void ldsm_x4(uint32_t* r, uint32_t addr) {
    asm volatile("ldmatrix.sync.aligned.m8n8.x4.shared.b16 {%0,%1,%2,%3}, [%4];"
                 : "=r"(r[0]), "=r"(r[1]), "=r"(r[2]), "=r"(r[3]) : "r"(addr));
}
__device__ __forceinline__ void mma_bf16(float* c, const uint32_t* a, uint32_t b0, uint32_t b1) {
    asm volatile("mma.sync.aligned.m16n8k16.row.col.f32.bf16.bf16.f32 "
                 "{%0,%1,%2,%3},{%4,%5,%6,%7},{%8,%9},{%0,%1,%2,%3};"
                 : "+f"(c[0]), "+f"(c[1]), "+f"(c[2]), "+f"(c[3])
                 : "r"(a[0]), "r"(a[1]), "r"(a[2]), "r"(a[3]), "r"(b0), "r"(b1));
}

// ====================================================================
// split-bf16 GEMM via mma.sync, CTA tile 128x256, warp tile 64x64.
// C[m,n] = sum_k A[m,k]*B[n,k] + bias[n]
// EPI: 0 = bias, 1 = bias+gelu, 2 = fused dual-gate RG-LRU epilogue
//      (B interleaved: col 2j = gate_x j, col 2j+1 = gate_a j)
// ====================================================================
template<int EPI>
__global__ void __launch_bounds__(256, 1) gemm_mma(
    const __nv_bfloat16* __restrict__ Ah, const __nv_bfloat16* __restrict__ Al, int lda, int az,
    const __nv_bfloat16* __restrict__ Bh, const __nv_bfloat16* __restrict__ Bl, int ldb, int bz,
    const float* __restrict__ bias, int biasz, const float* __restrict__ bias2,
    float* __restrict__ C, int ldc,
    float* __restrict__ C2,
    int K,
    const __nv_bfloat16* __restrict__ xch, const __nv_bfloat16* __restrict__ xcl,
    const float* __restrict__ a_param, const int* __restrict__ segpos)
{
    extern __shared__ __align__(1024) char smem[];
    const uint32_t sbase = smem_u32(smem);
    const int tid = threadIdx.x;
    const int wid = tid >> 5;
    const int lid = tid & 31;
    const int m0 = blockIdx.y * TM;
    const int n0 = blockIdx.x * TN;
    const int wm = wid & 1;      // 2 m-warps (64 rows each)
    const int wn = wid >> 1;     // 4 n-warps (64 cols each)
    const int nchunk = K / TKC;

    Ah   += (size_t)blockIdx.z * az;   Al   += (size_t)blockIdx.z * az;
    Bh   += (size_t)blockIdx.z * bz;   Bl   += (size_t)blockIdx.z * bz;
    if (EPI < 2) bias += (size_t)blockIdx.z * biasz;

    const __nv_bfloat16* Ah0 = Ah + (size_t)m0 * lda;
    const __nv_bfloat16* Al0 = Al + (size_t)m0 * lda;
    const __nv_bfloat16* Bh0 = Bh + (size_t)n0 * ldb;
    const __nv_bfloat16* Bl0 = Bl + (size_t)n0 * ldb;

    const int lr  = tid >> 3;          // loader row base (0..31)
    const int lc  = (tid & 7) * 16;    // loader byte col

    float acc[4][8][4];
#pragma unroll
    for (int i = 0; i < 4; i++)
#pragma unroll
        for (int j = 0; j < 8; j++)
#pragma unroll
            for (int q = 0; q < 4; q++) acc[i][j][q] = 0.0f;

#define LOAD_CHUNK(cc, ss)                                                            \
    {                                                                                 \
        const uint32_t st_ = sbase + (ss) * STAGE_BYTES;                              \
        const int k0_ = (cc) * TKC;                                                   \
        _Pragma("unroll")                                                             \
        for (int ii = 0; ii < 4; ii++) {                                              \
            const int r_ = lr + ii * 32;                                              \
            const uint32_t sw_ = (uint32_t)(r_ * 128 + (lc ^ ((r_ & 7) << 4)));       \
            cp16(st_ + AH_OFF + sw_, (const char*)(Ah0 + (size_t)r_ * lda + k0_) + lc); \
            cp16(st_ + AL_OFF + sw_, (const char*)(Al0 + (size_t)r_ * lda + k0_) + lc); \
        }                                                                             \
        _Pragma("unroll")                                                             \
        for (int ii = 0; ii < 8; ii++) {                                              \
            const int r_ = lr + ii * 32;                                              \
            const uint32_t sw_ = (uint32_t)(r_ * 128 + (lc ^ ((r_ & 7) << 4)));       \
            cp16(st_ + BH_OFF + sw_, (const char*)(Bh0 + (size_t)r_ * ldb + k0_) + lc); \
            cp16(st_ + BL_OFF + sw_, (const char*)(Bl0 + (size_t)r_ * ldb + k0_) + lc); \
        }                                                                             \
        asm volatile("cp.async.commit_group;");                                       \
    }

    LOAD_CHUNK(0, 0);

    // ldmatrix per-lane bases
    const int ra = wm * 64 + (lid & 15);
    const int rb = wn * 64 + (lid & 15);
    const int hi16 = (lid >> 4) * 16;
    const uint32_t axor = (uint32_t)((ra & 7) << 4);
    const uint32_t bxor = (uint32_t)((rb & 7) << 4);

    for (int c = 0; c < nchunk; c++) {
        const int s = c & 1;
        if (c + 1 < nchunk) {
            LOAD_CHUNK(c + 1, s ^ 1);
            asm volatile("cp.async.wait_group 1;");
        } else {
            asm volatile("cp.async.wait_group 0;");
        }
        __syncthreads();

        const uint32_t st = sbase + s * STAGE_BYTES;
        const uint32_t aRow = st + AH_OFF + (uint32_t)ra * 128;
        const uint32_t bRow = st + BH_OFF + (uint32_t)rb * 128;

#pragma unroll
        for (int k16 = 0; k16 < 4; k16++) {
            const uint32_t kb = (uint32_t)(k16 * 32 + hi16);
            uint32_t ah[4][4], al[4][4], b[16];
            const uint32_t aaddr = aRow + (kb ^ axor);
            const uint32_t baddr = bRow + (kb ^ bxor);
#pragma unroll
            for (int mf = 0; mf < 4; mf++) {
                ldsm_x4(ah[mf], aaddr + mf * 2048);
                ldsm_x4(al[mf], aaddr + AL_OFF - AH_OFF + mf * 2048);
            }
            // ---- B hi: Ah*Bh + Al*Bh ----
#pragma unroll
            for (int q = 0; q < 4; q++) ldsm_x4(b + q * 4, baddr + q * 2048);
#pragma unroll
            for (int mf = 0; mf < 4; mf++)
#pragma unroll
                for (int nf = 0; nf < 8; nf++) {
                    const int q = nf >> 1, r = nf & 1;
                    mma_bf16(acc[mf][nf], ah[mf], b[q * 4 + r], b[q * 4 + r + 2]);
                    mma_bf16(acc[mf][nf], al[mf], b[q * 4 + r], b[q * 4 + r + 2]);
                }
            // ---- B lo: Ah*Bl ----
#pragma unroll
            for (int q = 0; q < 4; q++) ldsm_x4(b + q * 4, baddr + (BL_OFF - BH_OFF) + q * 2048);
#pragma unroll
            for (int mf = 0; mf < 4; mf++)
#pragma unroll
                for (int nf = 0; nf < 8; nf++) {
                    const int q = nf >> 1, r = nf & 1;
                    mma_bf16(acc[mf][nf], ah[mf], b[q * 4 + r], b[q * 4 + r + 2]);
                }
        }
        __syncthreads();
    }
#undef LOAD_CHUNK

    // ---- epilogue ----
    const int rq = lid >> 2;
    const int cq = (lid & 3) * 2;
    if (EPI < 2) {
#pragma unroll
        for (int mf = 0; mf < 4; mf++) {
#pragma unroll
            for (int nf = 0; nf < 8; nf++) {
                const int row = m0 + wm * 64 + mf * 16 + rq;
                const int col = n0 + wn * 64 + nf * 8 + cq;
                const float b0 = bias[col], b1 = bias[col + 1];
                float v0 = acc[mf][nf][0] + b0;
                float v1 = acc[mf][nf][1] + b1;
                float v2 = acc[mf][nf][2] + b0;
                float v3 = acc[mf][nf][3] + b1;
                if (EPI == 1) {
                    v0 = gelu_tanh(v0); v1 = gelu_tanh(v1);
                    v2 = gelu_tanh(v2); v3 = gelu_tanh(v3);
                }
                *(float2*)&C[(size_t)row * ldc + col]       = make_float2(v0, v1);
                *(float2*)&C[(size_t)(row + 8) * ldc + col] = make_float2(v2, v3);
            }
        }
    } else {
        // fused RG-LRU gate epilogue: acc pair = (gx_pre, ga_pre) for column j
#pragma unroll
        for (int mf = 0; mf < 4; mf++) {
#pragma unroll
            for (int nf = 0; nf < 8; nf++) {
                const int row0 = m0 + wm * 64 + mf * 16 + rq;
                const int n = n0 + wn * 64 + nf * 8 + cq;   // even
                const int j = n >> 1;
                const int hd = blockIdx.z * DH + j;
                const float bgx = bias[j];
                const float bga = bias2[j];
                const float ap = a_param[hd];
                const float spa = (ap > 20.0f) ? ap : log1pf(expf(ap));
#pragma unroll
                for (int p = 0; p < 2; p++) {
                    const int r = row0 + p * 8;
                    const float gxp = acc[mf][nf][p * 2]     + bgx;
                    const float gap = acc[mf][nf][p * 2 + 1] + bga;
                    const size_t off = (size_t)r * DD + hd;
                    const float xcv = __bfloat162float(xch[off]) + __bfloat162float(xcl[off]);
                    const float gx = sigmoidf(gxp);
                    const float ga = sigmoidf(gap);
                    const float log_a = -8.0f * ga * spa;
                    const float a = expf(log_a);
                    const bool reset = (segpos[r] == 0);
                    const float mult = reset ? 1.0f
                        : sqrtf(fmaxf(1.0f - expf(2.0f * log_a), 0.0f));
                    C [off] = xcv * gx * mult;     // normed
                    C2[off] = reset ? 0.0f : a;    // a_scan
                }
            }
        }
    }
}

// ---------------- fp32 -> bf16 hi/lo split (vectorized x4) ----------------
__global__ void split4_kernel(const float* __restrict__ s,
                              __nv_bfloat16* __restrict__ hi, __nv_bfloat16* __restrict__ lo,
                              int n4)
{
    const int i4 = blockIdx.x * blockDim.x + threadIdx.x;
    if (i4 >= n4) return;
    const int i = i4 * 4;
    float4 v = *(const float4*)(s + i);
    __nv_bfloat16 h0 = __float2bfloat16(v.x), h1 = __float2bfloat16(v.y);
    __nv_bfloat16 h2 = __float2bfloat16(v.z), h3 = __float2bfloat16(v.w);
    __nv_bfloat16 l0 = __float2bfloat16(v.x - __bfloat162float(h0));
    __nv_bfloat16 l1 = __float2bfloat16(v.y - __bfloat162float(h1));
    __nv_bfloat16 l2 = __float2bfloat16(v.z - __bfloat162float(h2));
    __nv_bfloat16 l3 = __float2bfloat16(v.w - __bfloat162float(h3));
    __nv_bfloat162 hA = __nv_bfloat162(h0, h1), hB = __nv_bfloat162(h2, h3);
    __nv_bfloat162 lA = __nv_bfloat162(l0, l1), lB = __nv_bfloat162(l2, l3);
    *(uint2*)(hi + i) = make_uint2(*(uint32_t*)&hA, *(uint32_t*)&hB);
    *(uint2*)(lo + i) = make_uint2(*(uint32_t*)&lA, *(uint32_t*)&lB);
}

// ---------------- gate-weight interleave+transpose+split ----------------
// out row n = 2j+s (s=0: gx, s=1: ga), out[(h*512 + n)*256 + k] = w_s[h][k][j]
__global__ void split_gate_w(const float* __restrict__ gxw, const float* __restrict__ gaw,
                             __nv_bfloat16* __restrict__ hi, __nv_bfloat16* __restrict__ lo)
{
    const int idx = blockIdx.x * blockDim.x + threadIdx.x;
    if (idx >= HH * 512 * DH) return;
    const int k = idx % DH;
    const int n = (idx / DH) % 512;
    const int h = idx / (DH * 512);
    const int j = n >> 1;
    const float* w = (n & 1) ? gaw : gxw;
    const float v = w[((size_t)h * DH + k) * DH + j];
    const __nv_bfloat16 hv = __float2bfloat16(v);
    hi[idx] = hv;
    lo[idx] = __float2bfloat16(v - __bfloat162float(hv));
}

// ---------------- depthwise causal conv (TW=4), t-chunked, bf16 hi/lo out ----------------
__global__ void conv_kernel(const float* __restrict__ xp, const int* __restrict__ segpos,
                            const float* __restrict__ cw, const float* __restrict__ cb,
                            __nv_bfloat16* __restrict__ xch, __nv_bfloat16* __restrict__ xcl)
{
    const int gid = blockIdx.x * blockDim.x + threadIdx.x;
    if (gid >= BB * (TT / CT) * DD) return;
    const int d  = gid % DD;
    const int tc = (gid / DD) % (TT / CT);
    const int b  = gid / (DD * (TT / CT));
    const int t0 = tc * CT;
    const size_t base = ((size_t)b * TT + t0) * DD + d;

    const float w0 = cw[0 * DD + d], w1 = cw[1 * DD + d];
    const float w2 = cw[2 * DD + d], w3 = cw[3 * DD + d];
    const float bsv = cb[d];

    float xm1 = (t0 >= 1) ? xp[base - 1 * DD] : 0.0f;
    float xm2 = (t0 >= 2) ? xp[base - 2 * DD] : 0.0f;
    float xm3 = (t0 >= 3) ? xp[base - 3 * DD] : 0.0f;

#pragma unroll
    for (int i = 0; i < CT; i++) {
        const float cur = xp[base + (size_t)i * DD];
        const int sp = segpos[b * TT + t0 + i];
        float acc = bsv + cur * w3;
        if (sp >= 1) acc += xm1 * w2;
        if (sp >= 2) acc += xm2 * w1;
        if (sp >= 3) acc += xm3 * w0;
        const __nv_bfloat16 h = __float2bfloat16(acc);
        xch[base + (size_t)i * DD] = h;
        xcl[base + (size_t)i * DD] = __float2bfloat16(acc - __bfloat162float(h));
        xm3 = xm2; xm2 = xm1; xm1 = cur;
    }
}

// ---------------- chunked scan ----------------
__global__ void scan_pass1(const float* __restrict__ na, const float* __restrict__ nx)
{
    const long idx = (long)blockIdx.x * blockDim.x + threadIdx.x;
    if (idx >= (long)BB * NC * DD) return;
    const int d = (int)(idx % DD);
    const int c = (int)((idx / DD) % NC);
    const int b = (int)(idx / ((long)DD * NC));
    const long base = ((long)b * TT + (long)c * CL) * DD + d;
    float A = 1.0f, h = 0.0f;
#pragma unroll 4
    for (int t = 0; t < CL; t++) {
        const float a = na[base + (long)t * DD];
        const float x = nx[base + (long)t * DD];
        A *= a;
        h = a * h + x;
    }
    g_Ac[idx] = A;
    g_Bc[idx] = h;
}

__global__ void scan_pass2()
{
    const int idx = blockIdx.x * blockDim.x + threadIdx.x;
    if (idx >= BB * DD) return;
    const int d = idx % DD;
    const int b = idx / DD;
    float h = 0.0f;
#pragma unroll
    for (int c = 0; c < NC; c++) {
        const long off = ((long)b * NC + c) * DD + d;
        g_h0[off] = h;
        h = g_Ac[off] * h + g_Bc[off];
    }
}

__global__ void scan_pass3(const float* __restrict__ na, const float* __restrict__ nx,
                           const float* __restrict__ y,
                           __nv_bfloat16* __restrict__ zh, __nv_bfloat16* __restrict__ zl)
{
    const long idx = (long)blockIdx.x * blockDim.x + threadIdx.x;
    if (idx >= (long)BB * NC * DD) return;
    const int d = (int)(idx % DD);
    const int c = (int)((idx / DD) % NC);
    const int b = (int)(idx / ((long)DD * NC));
    const long base = ((long)b * TT + (long)c * CL) * DD + d;
    float h = g_h0[idx];
#pragma unroll 4
    for (int t = 0; t < CL; t++) {
        const long off = base + (long)t * DD;
        h = na[off] * h + nx[off];
        const float z = h * y[off];
        const __nv_bfloat16 zhi = __float2bfloat16(z);
        zh[off] = zhi;
        zl[off] = __float2bfloat16(z - __bfloat162float(zhi));
    }
}

// ---------------- launcher ----------------
extern "C" void kernel_launch(void* const* d_in, const int* in_sizes, int n_in,
                              void* d_out, int out_size)
{
    const float* x        = (const float*)d_in[0];
    const int*   segpos   = (const int*)  d_in[1];
    const float* Wy       = (const float*)d_in[2];
    const float* by       = (const float*)d_in[3];
    const float* Wx       = (const float*)d_in[4];
    const float* bx       = (const float*)d_in[5];
    const float* conv_w   = (const float*)d_in[6];
    const float* conv_b   = (const float*)d_in[7];
    const float* gx_w     = (const float*)d_in[8];
    const float* gx_b     = (const float*)d_in[9];
    const float* ga_w     = (const float*)d_in[10];
    const float* ga_b     = (const float*)d_in[11];
    const float* a_param  = (const float*)d_in[12];
    const float* Wout     = (const float*)d_in[13];
    const float* bout     = (const float*)d_in[14];
    float* out = (float*)d_out;

    float *py, *pxp, *pnx, *pna;
    cudaGetSymbolAddress((void**)&py,  g_y);
    cudaGetSymbolAddress((void**)&pxp, g_xp);
    cudaGetSymbolAddress((void**)&pnx, g_nx);
    cudaGetSymbolAddress((void**)&pna, g_na);
    __nv_bfloat16 *xh, *xl, *xch, *xcl, *zh, *zl, *wh, *wl, *gwh, *gwl;
    cudaGetSymbolAddress((void**)&xh,  g_xh_raw);
    cudaGetSymbolAddress((void**)&xl,  g_xl_raw);
    cudaGetSymbolAddress((void**)&xch, g_xch_raw);
    cudaGetSymbolAddress((void**)&xcl, g_xcl_raw);
    cudaGetSymbolAddress((void**)&zh,  g_zh_raw);
    cudaGetSymbolAddress((void**)&zl,  g_zl_raw);
    cudaGetSymbolAddress((void**)&wh,  g_wh_raw);
    cudaGetSymbolAddress((void**)&wl,  g_wl_raw);
    cudaGetSymbolAddress((void**)&gwh, g_gwh_raw);
    cudaGetSymbolAddress((void**)&gwl, g_gwl_raw);

    cudaFuncSetAttribute(gemm_mma<0>, cudaFuncAttributeMaxDynamicSharedMemorySize, SMEM_GEMM);
    cudaFuncSetAttribute(gemm_mma<1>, cudaFuncAttributeMaxDynamicSharedMemorySize, SMEM_GEMM);
    cudaFuncSetAttribute(gemm_mma<2>, cudaFuncAttributeMaxDynamicSharedMemorySize, SMEM_GEMM);

    // ---- splits ----
    split4_kernel<<<(NELEM/4 + 255)/256, 256>>>(x, xh, xl, NELEM/4);
    split4_kernel<<<(DD*DD/4 + 255)/256, 256>>>(Wy,   wh,           wl,           DD*DD/4);
    split4_kernel<<<(DD*DD/4 + 255)/256, 256>>>(Wx,   wh + DD*DD,   wl + DD*DD,   DD*DD/4);
    split4_kernel<<<(DD*DD/4 + 255)/256, 256>>>(Wout, wh + 2*DD*DD, wl + 2*DD*DD, DD*DD/4);
    split_gate_w<<<(HH*512*DH + 255)/256, 256>>>(gx_w, ga_w, gwh, gwl);

    const dim3 big_grid(DD / TN, BT / TM, 1);     // 8 x 64
    const dim3 gate_grid(512 / TN, BT / TM, HH);  // 2 x 64 x 8

    // 1) y = gelu(x @ Wy^T + by)
    gemm_mma<1><<<big_grid, 256, SMEM_GEMM>>>(
        xh, xl, DD, 0, wh, wl, DD, 0, by, 0, nullptr,
        py, DD, nullptr, DD, nullptr, nullptr, nullptr, nullptr);
    // 2) xp = x @ Wx^T + bx
    gemm_mma<0><<<big_grid, 256, SMEM_GEMM>>>(
        xh, xl, DD, 0, wh + DD*DD, wl + DD*DD, DD, 0, bx, 0, nullptr,
        pxp, DD, nullptr, DD, nullptr, nullptr, nullptr, nullptr);
    // 3) conv -> xc bf16 hi/lo
    conv_kernel<<<(BB*(TT/CT)*DD + 255)/256, 256>>>(pxp, segpos, conv_w, conv_b, xch, xcl);
    // 4) fused dual-gate GEMM + RG-LRU prep: writes normed -> nx, a_scan -> na
    gemm_mma<2><<<gate_grid, 256, SMEM_GEMM>>>(
        xch, xcl, DD, DH, gwh, gwl, DH, 512*DH, gx_b, DH, ga_b,
        pnx, DD, pna, DH, xch, xcl, a_param, segpos);
    // 5-7) chunked scan; pass3 emits z = h*y as bf16 hi/lo
    scan_pass1<<<(BB*NC*DD + 255)/256, 256>>>(pna, pnx);
    scan_pass2<<<(BB*DD + 255)/256, 256>>>();
    scan_pass3<<<(BB*NC*DD + 255)/256, 256>>>(pna, pnx, py, zh, zl);
    // 8) out = z @ Wout^T + bout
    gemm_mma<0><<<big_grid, 256, SMEM_GEMM>>>(
        zh, zl, DD, 0, wh + 2*DD*DD, wl + 2*DD*DD, DD, 0, bout, 0, nullptr,
        out, DD, nullptr, DD, nullptr, nullptr, nullptr, nullptr);
}

// round 6
// speedup vs baseline: 1.0999x; 1.0999x over previous
#include <cuda_runtime.h>
#include <cuda_bf16.h>
#include <stdint.h>
#include <math.h>

// ---------------- problem constants ----------------
#define BB   4
#define TT   2048
#define DD   2048
#define HH   8
#define DH   256
#define TW   4
#define BT   (BB*TT)          // 8192
#define NC   32               // scan chunks
#define CL   (TT/NC)          // 64
#define NELEM (BT*DD)         // 16,777,216
#define CT   16               // conv timesteps per thread

// ---------------- GEMM tiling ----------------
#define TM   128
#define TN   128
#define TKC  64                       // bf16 K elems per chunk (128B row)
#define AH_OFF 0
#define AL_OFF (TM*128)               // 16384
#define BH_OFF (2*TM*128)             // 32768
#define BL_OFF (2*TM*128 + TN*128)    // 49152
#define STAGE_BYTES (2*TM*128 + 2*TN*128)  // 65536
#define NSTAGE 3
#define SMEM_GEMM (NSTAGE*STAGE_BYTES)     // 196608

// ---------------- device scratch ----------------
__device__ float g_y [NELEM];
__device__ float g_xp[NELEM];
__device__ float g_nx[NELEM];
__device__ float g_na[NELEM];
__device__ float g_Ac[BB*NC*DD];
__device__ float g_Bc[BB*NC*DD];
__device__ float g_h0[BB*NC*DD];
// bf16 hi/lo buffers (uint4-backed for 16B alignment)
__device__ uint4 g_xh_raw [NELEM/8];
__device__ uint4 g_xl_raw [NELEM/8];
__device__ uint4 g_xch_raw[NELEM/8];
__device__ uint4 g_xcl_raw[NELEM/8];
__device__ uint4 g_zh_raw [NELEM/8];
__device__ uint4 g_zl_raw [NELEM/8];
__device__ uint4 g_wh_raw [3*DD*DD/8];
__device__ uint4 g_wl_raw [3*DD*DD/8];
__device__ uint4 g_gwh_raw[HH*512*DH/8];   // interleaved gate weights hi
__device__ uint4 g_gwl_raw[HH*512*DH/8];   // lo

// ---------------- helpers ----------------
__device__ __forceinline__ float gelu_tanh(float x) {
    float x3 = x * x * x;
    return 0.5f * x * (1.0f + tanhf(0.7978845608028654f * (x + 0.044715f * x3)));
}
__device__ __forceinline__ float sigmoidf(float x) { return 1.0f / (1.0f + expf(-x)); }

__device__ __forceinline__ uint32_t smem_u32(const void* p) {
    uint32_t a;
    asm("{ .reg .u64 t; cvta.to.shared.u64 t, %1; cvt.u32.u64 %0, t; }" : "=r"(a) : "l"(p));
    return a;
}
__device__ __forceinline__ void cp16(uint32_t dst, const void* src) {
    asm volatile("cp.async.cg.shared.global [%0], [%1], 16;" :: "r"(dst), "l"(src));
}
__device__ __forceinline__ void ldsm_x4(uint32_t* r, uint32_t addr) {
    asm volatile("ldmatrix.sync.aligned.m8n8.x4.shared.b16 {%0,%1,%2,%3}, [%4];"
                 : "=r"(r[0]), "=r"(r[1]), "=r"(r[2]), "=r"(r[3]) : "r"(addr));
}
__device__ __forceinline__ void mma_bf16(float* c, const uint32_t* a, uint32_t b0, uint32_t b1) {
    asm volatile("mma.sync.aligned.m16n8k16.row.col.f32.bf16.bf16.f32 "
                 "{%0,%1,%2,%3},{%4,%5,%6,%7},{%8,%9},{%0,%1,%2,%3};"
                 : "+f"(c[0]), "+f"(c[1]), "+f"(c[2]), "+f"(c[3])
                 : "r"(a[0]), "r"(a[1]), "r"(a[2]), "r"(a[3]), "r"(b0), "r"(b1));
}

// ====================================================================
// split-bf16 GEMM via mma.sync (3-stage cp.async pipeline +
// intra-chunk fragment double buffering)
// C[m,n] = sum_k A[m,k]*B[n,k] + bias[n]
// EPI: 0 = bias, 1 = bias+gelu, 2 = fused dual-gate RG-LRU epilogue
//      (B interleaved: col 2j = gate_x j, col 2j+1 = gate_a j)
// ====================================================================
template<int EPI>
__global__ void __launch_bounds__(256, 1) gemm_mma(
    const __nv_bfloat16* __restrict__ Ah, const __nv_bfloat16* __restrict__ Al, int lda, int az,
    const __nv_bfloat16* __restrict__ Bh, const __nv_bfloat16* __restrict__ Bl, int ldb, int bz,
    const float* __restrict__ bias, int biasz, const float* __restrict__ bias2,
    float* __restrict__ C, int ldc,
    float* __restrict__ C2,
    int K,
    const __nv_bfloat16* __restrict__ xch, const __nv_bfloat16* __restrict__ xcl,
    const float* __restrict__ a_param, const int* __restrict__ segpos)
{
    extern __shared__ __align__(1024) char smem[];
    const uint32_t sbase = smem_u32(smem);
    const int tid = threadIdx.x;
    const int wid = tid >> 5;
    const int lid = tid & 31;
    const int m0 = blockIdx.y * TM;
    const int n0 = blockIdx.x * TN;
    const int wm = wid & 1;      // 2 m-warps (64 rows each)
    const int wn = wid >> 1;     // 4 n-warps (32 cols each)
    const int nchunk = K / TKC;

    Ah   += (size_t)blockIdx.z * az;   Al   += (size_t)blockIdx.z * az;
    Bh   += (size_t)blockIdx.z * bz;   Bl   += (size_t)blockIdx.z * bz;
    if (EPI < 2) bias += (size_t)blockIdx.z * biasz;

    const __nv_bfloat16* Ah0 = Ah + (size_t)m0 * lda;
    const __nv_bfloat16* Al0 = Al + (size_t)m0 * lda;
    const __nv_bfloat16* Bh0 = Bh + (size_t)n0 * ldb;
    const __nv_bfloat16* Bl0 = Bl + (size_t)n0 * ldb;

    const int lr  = tid >> 3;          // loader row base (0..31)
    const int lc  = (tid & 7) * 16;    // loader byte col

    float acc[4][4][4];
#pragma unroll
    for (int i = 0; i < 4; i++)
#pragma unroll
        for (int j = 0; j < 4; j++)
#pragma unroll
            for (int q = 0; q < 4; q++) acc[i][j][q] = 0.0f;

#define LOAD_CHUNK(cc, ss)                                                            \
    {                                                                                 \
        const uint32_t st_ = sbase + (ss) * STAGE_BYTES;                              \
        const int k0_ = (cc) * TKC;                                                   \
        _Pragma("unroll")                                                             \
        for (int ii = 0; ii < 4; ii++) {                                              \
            const int r_ = lr + ii * 32;                                              \
            const uint32_t sw_ = (uint32_t)(r_ * 128 + (lc ^ ((r_ & 7) << 4)));       \
            cp16(st_ + AH_OFF + sw_, (const char*)(Ah0 + (size_t)r_ * lda + k0_) + lc); \
            cp16(st_ + AL_OFF + sw_, (const char*)(Al0 + (size_t)r_ * lda + k0_) + lc); \
            cp16(st_ + BH_OFF + sw_, (const char*)(Bh0 + (size_t)r_ * ldb + k0_) + lc); \
            cp16(st_ + BL_OFF + sw_, (const char*)(Bl0 + (size_t)r_ * ldb + k0_) + lc); \
        }                                                                             \
        asm volatile("cp.async.commit_group;");                                       \
    }

    // prologue: chunks 0,1 into stages 0,1
    LOAD_CHUNK(0, 0);
    LOAD_CHUNK(1, 1);

    // ldmatrix per-lane bases
    const int ra = wm * 64 + (lid & 15);
    const int rb = wn * 32 + (lid & 15);
    const int hi16 = (lid >> 4) * 16;
    const uint32_t axor = (uint32_t)((ra & 7) << 4);
    const uint32_t bxor = (uint32_t)((rb & 7) << 4);
    static const int bi0[4] = {0, 1, 4, 5};
    static const int bi1[4] = {2, 3, 6, 7};

    // double-buffered fragments
    uint32_t ah[2][4][4], al[2][4][4], bh[2][8], bl[2][8];

#define LOAD_FRAGS(pp, kk)                                              \
    {                                                                   \
        const uint32_t kb_ = (uint32_t)((kk) * 32 + hi16);              \
        const uint32_t aaddr_ = aRow + (kb_ ^ axor);                    \
        const uint32_t baddr_ = bRow + (kb_ ^ bxor);                    \
        _Pragma("unroll")                                               \
        for (int mf_ = 0; mf_ < 4; mf_++) {                             \
            ldsm_x4(ah[pp][mf_], aaddr_ + mf_ * 2048);                  \
            ldsm_x4(al[pp][mf_], aaddr_ + 16384 + mf_ * 2048);          \
        }                                                               \
        ldsm_x4(bh[pp],     baddr_);                                    \
        ldsm_x4(bh[pp] + 4, baddr_ + 2048);                             \
        ldsm_x4(bl[pp],     baddr_ + 16384);                            \
        ldsm_x4(bl[pp] + 4, baddr_ + 16384 + 2048);                     \
    }

    for (int c = 0; c < nchunk; c++) {
        asm volatile("cp.async.wait_group 1;");   // chunk c resident
        __syncthreads();                          // stage (c+2)%3 free
        if (c + 2 < nchunk) {
            LOAD_CHUNK(c + 2, (c + 2) % NSTAGE);
        } else {
            asm volatile("cp.async.commit_group;");
        }

        const uint32_t st = sbase + (c % NSTAGE) * STAGE_BYTES;
        const uint32_t aRow = st + AH_OFF + (uint32_t)ra * 128;
        const uint32_t bRow = st + BH_OFF + (uint32_t)rb * 128;

        LOAD_FRAGS(0, 0);
#pragma unroll
        for (int k16 = 0; k16 < 4; k16++) {
            const int cur = k16 & 1;
            if (k16 < 3) LOAD_FRAGS(cur ^ 1, k16 + 1);
#pragma unroll
            for (int mf = 0; mf < 4; mf++) {
#pragma unroll
                for (int nf = 0; nf < 4; nf++) {
                    mma_bf16(acc[mf][nf], ah[cur][mf], bh[cur][bi0[nf]], bh[cur][bi1[nf]]);
                    mma_bf16(acc[mf][nf], ah[cur][mf], bl[cur][bi0[nf]], bl[cur][bi1[nf]]);
                    mma_bf16(acc[mf][nf], al[cur][mf], bh[cur][bi0[nf]], bh[cur][bi1[nf]]);
                }
            }
        }
    }
#undef LOAD_FRAGS
#undef LOAD_CHUNK

    // ---- epilogue ----
    const int rq = lid >> 2;
    const int cq = (lid & 3) * 2;
    if (EPI < 2) {
#pragma unroll
        for (int mf = 0; mf < 4; mf++) {
#pragma unroll
            for (int nf = 0; nf < 4; nf++) {
                const int row = m0 + wm * 64 + mf * 16 + rq;
                const int col = n0 + wn * 32 + nf * 8 + cq;
                const float b0 = bias[col], b1 = bias[col + 1];
                float v0 = acc[mf][nf][0] + b0;
                float v1 = acc[mf][nf][1] + b1;
                float v2 = acc[mf][nf][2] + b0;
                float v3 = acc[mf][nf][3] + b1;
                if (EPI == 1) {
                    v0 = gelu_tanh(v0); v1 = gelu_tanh(v1);
                    v2 = gelu_tanh(v2); v3 = gelu_tanh(v3);
                }
                *(float2*)&C[(size_t)row * ldc + col]       = make_float2(v0, v1);
                *(float2*)&C[(size_t)(row + 8) * ldc + col] = make_float2(v2, v3);
            }
        }
    } else {
        // fused RG-LRU gate epilogue: acc pair = (gx_pre, ga_pre) for column j
#pragma unroll
        for (int mf = 0; mf < 4; mf++) {
#pragma unroll
            for (int nf = 0; nf < 4; nf++) {
                const int row0 = m0 + wm * 64 + mf * 16 + rq;
                const int n = n0 + wn * 32 + nf * 8 + cq;   // even
                const int j = n >> 1;
                const int hd = blockIdx.z * DH + j;
                const float bgx = bias[j];
                const float bga = bias2[j];
                const float ap = a_param[hd];
                const float spa = (ap > 20.0f) ? ap : log1pf(expf(ap));
#pragma unroll
                for (int p = 0; p < 2; p++) {
                    const int r = row0 + p * 8;
                    const float gxp = acc[mf][nf][p * 2]     + bgx;
                    const float gap = acc[mf][nf][p * 2 + 1] + bga;
                    const size_t off = (size_t)r * DD + hd;
                    const float xcv = __bfloat162float(xch[off]) + __bfloat162float(xcl[off]);
                    const float gx = sigmoidf(gxp);
                    const float ga = sigmoidf(gap);
                    const float log_a = -8.0f * ga * spa;
                    const float a = expf(log_a);
                    const bool reset = (segpos[r] == 0);
                    const float mult = reset ? 1.0f
                        : sqrtf(fmaxf(1.0f - expf(2.0f * log_a), 0.0f));
                    C [off] = xcv * gx * mult;     // normed
                    C2[off] = reset ? 0.0f : a;    // a_scan
                }
            }
        }
    }
}

// ---------------- fp32 -> bf16 hi/lo split (vectorized x4) ----------------
__global__ void split4_kernel(const float* __restrict__ s,
                              __nv_bfloat16* __restrict__ hi, __nv_bfloat16* __restrict__ lo,
                              int n4)
{
    const int i4 = blockIdx.x * blockDim.x + threadIdx.x;
    if (i4 >= n4) return;
    const int i = i4 * 4;
    float4 v = *(const float4*)(s + i);
    __nv_bfloat16 h0 = __float2bfloat16(v.x), h1 = __float2bfloat16(v.y);
    __nv_bfloat16 h2 = __float2bfloat16(v.z), h3 = __float2bfloat16(v.w);
    __nv_bfloat16 l0 = __float2bfloat16(v.x - __bfloat162float(h0));
    __nv_bfloat16 l1 = __float2bfloat16(v.y - __bfloat162float(h1));
    __nv_bfloat16 l2 = __float2bfloat16(v.z - __bfloat162float(h2));
    __nv_bfloat16 l3 = __float2bfloat16(v.w - __bfloat162float(h3));
    __nv_bfloat162 hA = __nv_bfloat162(h0, h1), hB = __nv_bfloat162(h2, h3);
    __nv_bfloat162 lA = __nv_bfloat162(l0, l1), lB = __nv_bfloat162(l2, l3);
    *(uint2*)(hi + i) = make_uint2(*(uint32_t*)&hA, *(uint32_t*)&hB);
    *(uint2*)(lo + i) = make_uint2(*(uint32_t*)&lA, *(uint32_t*)&lB);
}

// ---------------- gate-weight interleave+transpose+split ----------------
// out row n = 2j+s (s=0: gx, s=1: ga), out[(h*512 + n)*256 + k] = w_s[h][k][j]
__global__ void split_gate_w(const float* __restrict__ gxw, const float* __restrict__ gaw,
                             __nv_bfloat16* __restrict__ hi, __nv_bfloat16* __restrict__ lo)
{
    const int idx = blockIdx.x * blockDim.x + threadIdx.x;
    if (idx >= HH * 512 * DH) return;
    const int k = idx % DH;
    const int n = (idx / DH) % 512;
    const int h = idx / (DH * 512);
    const int j = n >> 1;
    const float* w = (n & 1) ? gaw : gxw;
    const float v = w[((size_t)h * DH + k) * DH + j];
    const __nv_bfloat16 hv = __float2bfloat16(v);
    hi[idx] = hv;
    lo[idx] = __float2bfloat16(v - __bfloat162float(hv));
}

// ---------------- depthwise causal conv (TW=4), t-chunked, bf16 hi/lo out ----------------
__global__ void conv_kernel(const float* __restrict__ xp, const int* __restrict__ segpos,
                            const float* __restrict__ cw, const float* __restrict__ cb,
                            __nv_bfloat16* __restrict__ xch, __nv_bfloat16* __restrict__ xcl)
{
    const int gid = blockIdx.x * blockDim.x + threadIdx.x;
    if (gid >= BB * (TT / CT) * DD) return;
    const int d  = gid % DD;
    const int tc = (gid / DD) % (TT / CT);
    const int b  = gid / (DD * (TT / CT));
    const int t0 = tc * CT;
    const size_t base = ((size_t)b * TT + t0) * DD + d;

    const float w0 = cw[0 * DD + d], w1 = cw[1 * DD + d];
    const float w2 = cw[2 * DD + d], w3 = cw[3 * DD + d];
    const float bsv = cb[d];

    float xm1 = (t0 >= 1) ? xp[base - 1 * DD] : 0.0f;
    float xm2 = (t0 >= 2) ? xp[base - 2 * DD] : 0.0f;
    float xm3 = (t0 >= 3) ? xp[base - 3 * DD] : 0.0f;

#pragma unroll
    for (int i = 0; i < CT; i++) {
        const float cur = xp[base + (size_t)i * DD];
        const int sp = segpos[b * TT + t0 + i];
        float acc = bsv + cur * w3;
        if (sp >= 1) acc += xm1 * w2;
        if (sp >= 2) acc += xm2 * w1;
        if (sp >= 3) acc += xm3 * w0;
        const __nv_bfloat16 h = __float2bfloat16(acc);
        xch[base + (size_t)i * DD] = h;
        xcl[base + (size_t)i * DD] = __float2bfloat16(acc - __bfloat162float(h));
        xm3 = xm2; xm2 = xm1; xm1 = cur;
    }
}

// ---------------- chunked scan ----------------
__global__ void scan_pass1(const float* __restrict__ na, const float* __restrict__ nx)
{
    const long idx = (long)blockIdx.x * blockDim.x + threadIdx.x;
    if (idx >= (long)BB * NC * DD) return;
    const int d = (int)(idx % DD);
    const int c = (int)((idx / DD) % NC);
    const int b = (int)(idx / ((long)DD * NC));
    const long base = ((long)b * TT + (long)c * CL) * DD + d;
    float A = 1.0f, h = 0.0f;
#pragma unroll 4
    for (int t = 0; t < CL; t++) {
        const float a = na[base + (long)t * DD];
        const float x = nx[base + (long)t * DD];
        A *= a;
        h = a * h + x;
    }
    g_Ac[idx] = A;
    g_Bc[idx] = h;
}

__global__ void scan_pass2()
{
    const int idx = blockIdx.x * blockDim.x + threadIdx.x;
    if (idx >= BB * DD) return;
    const int d = idx % DD;
    const int b = idx / DD;
    float h = 0.0f;
#pragma unroll
    for (int c = 0; c < NC; c++) {
        const long off = ((long)b * NC + c) * DD + d;
        g_h0[off] = h;
        h = g_Ac[off] * h + g_Bc[off];
    }
}

__global__ void scan_pass3(const float* __restrict__ na, const float* __restrict__ nx,
                           const float* __restrict__ y,
                           __nv_bfloat16* __restrict__ zh, __nv_bfloat16* __restrict__ zl)
{
    const long idx = (long)blockIdx.x * blockDim.x + threadIdx.x;
    if (idx >= (long)BB * NC * DD) return;
    const int d = (int)(idx % DD);
    const int c = (int)((idx / DD) % NC);
    const int b = (int)(idx / ((long)DD * NC));
    const long base = ((long)b * TT + (long)c * CL) * DD + d;
    float h = g_h0[idx];
#pragma unroll 4
    for (int t = 0; t < CL; t++) {
        const long off = base + (long)t * DD;
        h = na[off] * h + nx[off];
        const float z = h * y[off];
        const __nv_bfloat16 zhi = __float2bfloat16(z);
        zh[off] = zhi;
        zl[off] = __float2bfloat16(z - __bfloat162float(zhi));
    }
}

// ---------------- launcher ----------------
extern "C" void kernel_launch(void* const* d_in, const int* in_sizes, int n_in,
                              void* d_out, int out_size)
{
    const float* x        = (const float*)d_in[0];
    const int*   segpos   = (const int*)  d_in[1];
    const float* Wy       = (const float*)d_in[2];
    const float* by       = (const float*)d_in[3];
    const float* Wx       = (const float*)d_in[4];
    const float* bx       = (const float*)d_in[5];
    const float* conv_w   = (const float*)d_in[6];
    const float* conv_b   = (const float*)d_in[7];
    const float* gx_w     = (const float*)d_in[8];
    const float* gx_b     = (const float*)d_in[9];
    const float* ga_w     = (const float*)d_in[10];
    const float* ga_b     = (const float*)d_in[11];
    const float* a_param  = (const float*)d_in[12];
    const float* Wout     = (const float*)d_in[13];
    const float* bout     = (const float*)d_in[14];
    float* out = (float*)d_out;

    float *py, *pxp, *pnx, *pna;
    cudaGetSymbolAddress((void**)&py,  g_y);
    cudaGetSymbolAddress((void**)&pxp, g_xp);
    cudaGetSymbolAddress((void**)&pnx, g_nx);
    cudaGetSymbolAddress((void**)&pna, g_na);
    __nv_bfloat16 *xh, *xl, *xch, *xcl, *zh, *zl, *wh, *wl, *gwh, *gwl;
    cudaGetSymbolAddress((void**)&xh,  g_xh_raw);
    cudaGetSymbolAddress((void**)&xl,  g_xl_raw);
    cudaGetSymbolAddress((void**)&xch, g_xch_raw);
    cudaGetSymbolAddress((void**)&xcl, g_xcl_raw);
    cudaGetSymbolAddress((void**)&zh,  g_zh_raw);
    cudaGetSymbolAddress((void**)&zl,  g_zl_raw);
    cudaGetSymbolAddress((void**)&wh,  g_wh_raw);
    cudaGetSymbolAddress((void**)&wl,  g_wl_raw);
    cudaGetSymbolAddress((void**)&gwh, g_gwh_raw);
    cudaGetSymbolAddress((void**)&gwl, g_gwl_raw);

    cudaFuncSetAttribute(gemm_mma<0>, cudaFuncAttributeMaxDynamicSharedMemorySize, SMEM_GEMM);
    cudaFuncSetAttribute(gemm_mma<1>, cudaFuncAttributeMaxDynamicSharedMemorySize, SMEM_GEMM);
    cudaFuncSetAttribute(gemm_mma<2>, cudaFuncAttributeMaxDynamicSharedMemorySize, SMEM_GEMM);

    // ---- splits ----
    split4_kernel<<<(NELEM/4 + 255)/256, 256>>>(x, xh, xl, NELEM/4);
    split4_kernel<<<(DD*DD/4 + 255)/256, 256>>>(Wy,   wh,           wl,           DD*DD/4);
    split4_kernel<<<(DD*DD/4 + 255)/256, 256>>>(Wx,   wh + DD*DD,   wl + DD*DD,   DD*DD/4);
    split4_kernel<<<(DD*DD/4 + 255)/256, 256>>>(Wout, wh + 2*DD*DD, wl + 2*DD*DD, DD*DD/4);
    split_gate_w<<<(HH*512*DH + 255)/256, 256>>>(gx_w, ga_w, gwh, gwl);

    const dim3 big_grid(DD / TN, BT / TM, 1);     // 16 x 64
    const dim3 gate_grid(512 / TN, BT / TM, HH);  // 4 x 64 x 8

    // 1) y = gelu(x @ Wy^T + by)
    gemm_mma<1><<<big_grid, 256, SMEM_GEMM>>>(
        xh, xl, DD, 0, wh, wl, DD, 0, by, 0, nullptr,
        py, DD, nullptr, DD, nullptr, nullptr, nullptr, nullptr);
    // 2) xp = x @ Wx^T + bx
    gemm_mma<0><<<big_grid, 256, SMEM_GEMM>>>(
        xh, xl, DD, 0, wh + DD*DD, wl + DD*DD, DD, 0, bx, 0, nullptr,
        pxp, DD, nullptr, DD, nullptr, nullptr, nullptr, nullptr);
    // 3) conv -> xc bf16 hi/lo
    conv_kernel<<<(BB*(TT/CT)*DD + 255)/256, 256>>>(pxp, segpos, conv_w, conv_b, xch, xcl);
    // 4) fused dual-gate GEMM + RG-LRU prep: writes normed -> nx, a_scan -> na
    gemm_mma<2><<<gate_grid, 256, SMEM_GEMM>>>(
        xch, xcl, DD, DH, gwh, gwl, DH, 512*DH, gx_b, DH, ga_b,
        pnx, DD, pna, DH, xch, xcl, a_param, segpos);
    // 5-7) chunked scan; pass3 emits z = h*y as bf16 hi/lo
    scan_pass1<<<(BB*NC*DD + 255)/256, 256>>>(pna, pnx);
    scan_pass2<<<(BB*DD + 255)/256, 256>>>();
    scan_pass3<<<(BB*NC*DD + 255)/256, 256>>>(pna, pnx, py, zh, zl);
    // 8) out = z @ Wout^T + bout
    gemm_mma<0><<<big_grid, 256, SMEM_GEMM>>>(
        zh, zl, DD, 0, wh + 2*DD*DD, wl + 2*DD*DD, DD, 0, bout, 0, nullptr,
        out, DD, nullptr, DD, nullptr, nullptr, nullptr, nullptr);
}